// round 1
// baseline (speedup 1.0000x reference)
#include <cuda_runtime.h>
#include <cuda_bf16.h>

// ChannelPruner: out[b,o,h,w] = sum_c w[o,c] * x[b,c,h,w]
// w is extremely sparse per-row (identity with pruned rows zeroed), but we
// build the per-row sparse structure at runtime from the actual weight input,
// so the kernel is correct for ANY 256x256 w.
//
// x:  (32, 256, 56, 56) fp32   -> 25,690,112 floats
// w:  (256, 256, 1, 1)  fp32   -> 65,536 floats
// out: same shape as x.

#define N_CH     256
#define BATCH    32
#define HW       3136          // 56*56
#define HW4      784           // HW / 4 (float4 per plane)
#define TOTAL4   (BATCH * N_CH * HW4)   // 6,422,528 float4 outputs

// Scratch: per-row compacted (col, val) lists + counts. Overwritten fully on
// every launch (deterministic, graph-replay safe, no allocation).
__device__ int   g_nnz[N_CH];
__device__ int   g_cols[N_CH * N_CH];
__device__ float g_vals[N_CH * N_CH];

// ---------------------------------------------------------------------------
// Kernel 1: one warp per weight row, compact nonzeros via warp scan.
// ---------------------------------------------------------------------------
__global__ __launch_bounds__(256) void build_csr(const float* __restrict__ w) {
    const int row  = blockIdx.x * 8 + (threadIdx.x >> 5);   // 32 blocks * 8 warps
    const int lane = threadIdx.x & 31;
    const float* wr = w + row * N_CH;

    float v[8];
    int cnt = 0;
    const int base = lane * 8;
#pragma unroll
    for (int k = 0; k < 8; k++) {
        v[k] = wr[base + k];
        if (v[k] != 0.0f) cnt++;
    }

    // inclusive warp scan of cnt
    int scan = cnt;
#pragma unroll
    for (int d = 1; d < 32; d <<= 1) {
        int t = __shfl_up_sync(0xffffffffu, scan, d);
        if (lane >= d) scan += t;
    }
    const int total = __shfl_sync(0xffffffffu, scan, 31);
    int p = row * N_CH + (scan - cnt);   // exclusive offset

#pragma unroll
    for (int k = 0; k < 8; k++) {
        if (v[k] != 0.0f) {
            g_cols[p] = base + k;
            g_vals[p] = v[k];
            p++;
        }
    }
    if (lane == 31) g_nnz[row] = total;
}

// ---------------------------------------------------------------------------
// Kernel 2: one thread per output float4. For this dataset nnz is 0 or 1,
// so each thread does at most one 16B read plus one 16B write.
// ---------------------------------------------------------------------------
__global__ __launch_bounds__(256) void apply_sparse(const float4* __restrict__ x,
                                                    float4* __restrict__ out) {
    const int gid = blockIdx.x * 256 + threadIdx.x;
    if (gid >= TOTAL4) return;

    const int bo  = gid / HW4;            // plane index = b*256 + o
    const int hw4 = gid - bo * HW4;
    const int o   = bo & (N_CH - 1);
    const int b   = bo >> 8;

    const int n = __ldg(&g_nnz[o]);
    float4 acc = make_float4(0.f, 0.f, 0.f, 0.f);

    const float4* xb = x + (size_t)b * (N_CH * HW4);
    const int rbase = o * N_CH;
    for (int j = 0; j < n; j++) {
        const int   c = __ldg(&g_cols[rbase + j]);
        const float v = __ldg(&g_vals[rbase + j]);
        const float4 xv = __ldg(&xb[c * HW4 + hw4]);
        acc.x += v * xv.x;
        acc.y += v * xv.y;
        acc.z += v * xv.z;
        acc.w += v * xv.w;
    }
    out[gid] = acc;
}

extern "C" void kernel_launch(void* const* d_in, const int* in_sizes, int n_in,
                              void* d_out, int out_size) {
    const float* x = (const float*)d_in[0];
    const float* w = (const float*)d_in[1];
    float* out = (float*)d_out;

    build_csr<<<32, 256>>>(w);
    apply_sparse<<<(TOTAL4 + 255) / 256, 256>>>((const float4*)x, (float4*)out);
}

// round 2
// speedup vs baseline: 1.1117x; 1.1117x over previous
#include <cuda_runtime.h>
#include <cuda_bf16.h>

// ChannelPruner: out[b,o,h,w] = sum_c w[o,c] * x[b,c,h,w]
// x: (32, 256, 56, 56) fp32, w: (256,256,1,1) fp32 (very sparse rows).
// Fused single kernel: each block owns one (b,o) output plane.
//   Prologue: compact nonzeros of w row o into smem (deterministic ballot scan).
//   Body:     each thread produces 4 float4 outputs -> MLP=4 independent LDG.128
//             per source channel, fully coalesced reads and writes.
// Correct for ANY 256x256 w (structure discovered at runtime).

#define N_CH   256
#define BATCH  32
#define HW4    784                    // (56*56)/4 float4 per plane
#define NPLANE (BATCH * N_CH)         // 8192 planes / blocks

__global__ __launch_bounds__(256, 8) void prune_fused(const float4* __restrict__ x,
                                                      const float*  __restrict__ w,
                                                      float4* __restrict__ out) {
    __shared__ int   s_cols[N_CH];
    __shared__ float s_vals[N_CH];
    __shared__ int   s_warp_off[9];   // exclusive offsets per warp (+ total)

    const int tid  = threadIdx.x;
    const int lane = tid & 31;
    const int wid  = tid >> 5;

    const int bo = blockIdx.x;        // plane index
    const int o  = bo & (N_CH - 1);

    // ---- prologue: deterministic compaction of w row o ----
    const float wv = __ldg(&w[o * N_CH + tid]);
    const unsigned mask = __ballot_sync(0xffffffffu, wv != 0.0f);
    const int wcnt = __popc(mask);

    if (lane == 0) s_warp_off[wid + 1] = wcnt;
    __syncthreads();
    if (tid == 0) {
        int acc = 0;
        s_warp_off[0] = 0;
#pragma unroll
        for (int i = 0; i < 8; i++) { acc += s_warp_off[i + 1]; s_warp_off[i + 1] = acc; }
    }
    __syncthreads();

    if (wv != 0.0f) {
        const int pos = s_warp_off[wid] + __popc(mask & ((1u << lane) - 1u));
        s_cols[pos] = tid;
        s_vals[pos] = wv;
    }
    __syncthreads();

    const int nnz = s_warp_off[8];

    // ---- body: 4 float4 outputs per thread, idx = tid + k*256 ----
    float4 acc0 = make_float4(0.f, 0.f, 0.f, 0.f);
    float4 acc1 = acc0, acc2 = acc0, acc3 = acc0;

    const float4* xb = x + (size_t)(bo >> 8) * (N_CH * HW4);   // batch base
    const bool has3 = (tid + 768) < HW4;                        // tid < 16

    for (int j = 0; j < nnz; j++) {
        const int   c = s_cols[j];
        const float v = s_vals[j];
        const float4* xc = xb + (size_t)c * HW4 + tid;
        // 4 independent loads (MLP=4)
        const float4 a = __ldg(xc);
        const float4 b = __ldg(xc + 256);
        const float4 d = __ldg(xc + 512);
        float4 e = make_float4(0.f, 0.f, 0.f, 0.f);
        if (has3) e = __ldg(xc + 768);

        acc0.x += v * a.x; acc0.y += v * a.y; acc0.z += v * a.z; acc0.w += v * a.w;
        acc1.x += v * b.x; acc1.y += v * b.y; acc1.z += v * b.z; acc1.w += v * b.w;
        acc2.x += v * d.x; acc2.y += v * d.y; acc2.z += v * d.z; acc2.w += v * d.w;
        acc3.x += v * e.x; acc3.y += v * e.y; acc3.z += v * e.z; acc3.w += v * e.w;
    }

    float4* ob = out + (size_t)bo * HW4 + tid;
    ob[0]   = acc0;
    ob[256] = acc1;
    ob[512] = acc2;
    if (has3) ob[768] = acc3;
}

extern "C" void kernel_launch(void* const* d_in, const int* in_sizes, int n_in,
                              void* d_out, int out_size) {
    const float4* x = (const float4*)d_in[0];
    const float*  w = (const float*)d_in[1];
    float4* out = (float4*)d_out;

    prune_fused<<<NPLANE, 256>>>(x, w, out);
}